// round 7
// baseline (speedup 1.0000x reference)
#include <cuda_runtime.h>
#include <math.h>

#define NC 64
#define NF 128
#define NS 192
#define RPB 8        // rays per block, 1 warp each

// compare-exchange a pair of registers; 'up' => a gets min
#define CEPAIR(a, b, up) { float _mn = fminf(a, b), _mx = fmaxf(a, b); \
                           a = (up) ? _mn : _mx; b = (up) ? _mx : _mn; }

__global__ __launch_bounds__(256, 5) void gridnerf_kernel(
    const float* __restrict__ ro,      // [N,3]
    const float* __restrict__ rd,      // [N,3]
    const float* __restrict__ cw,      // [N,NC]
    const float* __restrict__ ct,      // [N,NC]
    const float* __restrict__ uu_in,   // [N,NF]
    const float* __restrict__ colors,  // [N,NS,3]
    const float* __restrict__ dens,    // [N,NS]
    float* __restrict__ out_rgb,       // [N,3]
    float* __restrict__ out_depth,     // [N]
    float* __restrict__ out_op,        // [N]
    float* __restrict__ out_fp,        // [N,NS,3]
    int nrays)
{
    const int L   = threadIdx.x & 31;
    const int w   = threadIdx.x >> 5;
    const int ray = blockIdx.x * RPB + w;
    if (ray >= nrays) return;          // warp-uniform exit; no block syncs used

    __shared__ float sh_cdf[RPB][128]; // [0..64] cdf, [65..127] +inf pad
    __shared__ float sh_ct [RPB][64];
    __shared__ int   sh_lo [RPB][192]; // [0..127] lo (sorted), [128..191] INT_MAX pad
    __shared__ float sh_t  [RPB][192];
    __shared__ float sh_w  [RPB][192];

    float* cdf = sh_cdf[w];
    float* sct = sh_ct[w];
    int*   slo = sh_lo[w];
    float* st  = sh_t[w];
    float* sw  = sh_w[w];

    // ---- A: global loads (coalesced / vectorized) ----
    const float4 u4 = ((const float4*)(uu_in + (size_t)ray * NF))[L];
    float v0 = u4.x, v1 = u4.y, v2 = u4.z, v3 = u4.w;   // elements 4L..4L+3

    const float2 cw2 = ((const float2*)(cw + (size_t)ray * NC))[L];
    const float2 ct2 = ((const float2*)(ct + (size_t)ray * NC))[L];

    const float ox = ro[3 * ray + 0], oy = ro[3 * ray + 1], oz = ro[3 * ray + 2];
    const float dx = rd[3 * ray + 0], dy = rd[3 * ray + 1], dz = rd[3 * ray + 2];
    const float dnorm = sqrtf(dx * dx + dy * dy + dz * dz);

    // ---- B: cdf build (pair-per-lane warp scan) ----
    {
        const float a  = cw2.x + 1e-5f;
        const float b  = cw2.y + 1e-5f;
        const float ps = a + b;
        float inc = ps;
        #pragma unroll
        for (int off = 1; off < 32; off <<= 1) {
            float n = __shfl_up_sync(0xffffffffu, inc, off);
            if (L >= off) inc += n;
        }
        const float total = __shfl_sync(0xffffffffu, inc, 31);
        const float invt  = 1.f / total;
        const float excl  = inc - ps;
        cdf[2 * L + 1] = (excl + a) * invt;
        cdf[2 * L + 2] = (excl + ps) * invt;
        if (L == 0) cdf[0] = 0.f;
        cdf[65 + L] = 3.4e38f;
        if (L < 31) cdf[97 + L] = 3.4e38f;
        sct[2 * L]     = ct2.x;
        sct[2 * L + 1] = ct2.y;
        slo[128 + L] = 0x7fffffff;
        slo[160 + L] = 0x7fffffff;
    }
    __syncwarp();

    // ---- C: bitonic sort of 128 u, 4 elements/thread (e = 4L+i) ----
    #pragma unroll
    for (int k = 2; k <= 128; k <<= 1) {
        #pragma unroll
        for (int j = k >> 1; j >= 4; j >>= 1) {
            const bool up = ((L & (k >> 2)) == 0);   // k>=8 here
            const bool lw = ((L & (j >> 2)) == 0);
            const bool km = (up == lw);
            float w0 = __shfl_xor_sync(0xffffffffu, v0, j >> 2);
            float w1 = __shfl_xor_sync(0xffffffffu, v1, j >> 2);
            float w2 = __shfl_xor_sync(0xffffffffu, v2, j >> 2);
            float w3 = __shfl_xor_sync(0xffffffffu, v3, j >> 2);
            v0 = km ? fminf(v0, w0) : fmaxf(v0, w0);
            v1 = km ? fminf(v1, w1) : fmaxf(v1, w1);
            v2 = km ? fminf(v2, w2) : fmaxf(v2, w2);
            v3 = km ? fminf(v3, w3) : fmaxf(v3, w3);
        }
        if (k >= 4) {  // j = 2 : pairs (v0,v2), (v1,v3)
            const bool up = (k == 4) ? ((L & 1) == 0) : ((L & (k >> 2)) == 0);
            CEPAIR(v0, v2, up); CEPAIR(v1, v3, up);
        }
        // j = 1 : pairs (v0,v1), (v2,v3)
        if (k == 2) {
            CEPAIR(v0, v1, true);  CEPAIR(v2, v3, false);
        } else {
            const bool up = (k == 4) ? ((L & 1) == 0) : ((L & (k >> 2)) == 0);
            CEPAIR(v0, v1, up);    CEPAIR(v2, v3, up);
        }
    }

    // ---- D: inverse-CDF on sorted u + rank-merge scatter of fine values ----
    {
        float va[4] = {v0, v1, v2, v3};
        #pragma unroll
        for (int i = 0; i < 4; i++) {
            const float uu = va[i];
            int p = 0;                                // invariant cdf[p] <= uu
            if (cdf[64]     <= uu) p = 64;
            if (cdf[p + 32] <= uu) p += 32;
            if (cdf[p + 16] <= uu) p += 16;
            if (cdf[p + 8]  <= uu) p += 8;
            if (cdf[p + 4]  <= uu) p += 4;
            if (cdf[p + 2]  <= uu) p += 2;
            if (cdf[p + 1]  <= uu) p += 1;
            const int lo    = p + 1;                  // searchsorted(right)
            const int below = min(p, NC - 1);
            const int above = min(lo, NC - 1);
            const float cb = cdf[below], ca = cdf[above];
            const float tb = sct[below], ta = sct[above];
            float denom = ca - cb;
            if (denom < 1e-5f) denom = 1.f;
            const float tt = (uu - cb) / denom;
            const float fv = tb + tt * (ta - tb);
            const int e = 4 * L + i;                  // sorted rank
            slo[e] = lo;                              // monotone
            st[e + min(lo, NC)] = fv;
        }
    }
    __syncwarp();

    // ---- E: coarse ranks (count fine with lo <= i), 2 per lane ----
    #pragma unroll
    for (int h = 0; h < 2; h++) {
        const int i = L + 32 * h;
        int r = 0;
        if (slo[127]    <= i) r = 128;
        if (slo[r + 63] <= i) r += 64;
        if (slo[r + 31] <= i) r += 32;
        if (slo[r + 15] <= i) r += 16;
        if (slo[r + 7]  <= i) r += 8;
        if (slo[r + 3]  <= i) r += 4;
        if (slo[r + 1]  <= i) r += 2;
        if (slo[r]      <= i) r += 1;
        st[i + r] = sct[i];
    }
    __syncwarp();

    // ---- F: alpha + transmittance (thread owns samples 6L..6L+5) ----
    float dep = 0.f, op = 0.f;
    {
        float tb[6], alpha[6];
        #pragma unroll
        for (int i = 0; i < 6; i++) tb[i] = st[6 * L + i];
        const float t6 = (L < 31) ? st[6 * L + 6] : 0.f;

        // densities: direct blocked global load (no shared staging)
        const float* dvp = dens + (size_t)ray * NS + 6 * L;
        const float2 dva = *(const float2*)(dvp + 0);
        const float2 dvb = *(const float2*)(dvp + 2);
        const float2 dvc = *(const float2*)(dvp + 4);
        const float dvv[6] = {dva.x, dva.y, dvb.x, dvb.y, dvc.x, dvc.y};

        float run = 1.f;
        #pragma unroll
        for (int i = 0; i < 6; i++) {
            float dist;
            if (i < 5)          dist = tb[i + 1] - tb[i];
            else if (L == 31)   dist = 1e10f;
            else                dist = t6 - tb[5];
            dist *= dnorm;
            alpha[i] = 1.f - __expf(-dvv[i] * dist);
            run *= (1.f - alpha[i] + 1e-10f);
        }
        // warp multiplicative exclusive scan of per-thread products
        float inc = run;
        #pragma unroll
        for (int off = 1; off < 32; off <<= 1) {
            float n = __shfl_up_sync(0xffffffffu, inc, off);
            if (L >= off) inc *= n;
        }
        float wex = __shfl_up_sync(0xffffffffu, inc, 1);
        if (L == 0) wex = 1.f;

        float run2 = wex;                 // running transmittance
        #pragma unroll
        for (int i = 0; i < 6; i++) {
            const float wt = alpha[i] * run2;
            sw[6 * L + i] = wt;
            dep += wt * tb[i];
            op  += wt;
            run2 *= (1.f - alpha[i] + 1e-10f);
        }
    }
    __syncwarp();

    // ---- G: fused coalesced fp stores + rgb accumulation (colors inline) ----
    float A0 = 0.f, A1 = 0.f, A2 = 0.f;
    {
        const int rho = (2 * L) % 3;
        const float oR0 = (rho == 0) ? ox : ((rho == 1) ? oy : oz);
        const float oR1 = (rho == 0) ? oy : ((rho == 1) ? oz : ox);
        const float oR2 = (rho == 0) ? oz : ((rho == 1) ? ox : oy);
        const float dR0 = (rho == 0) ? dx : ((rho == 1) ? dy : dz);
        const float dR1 = (rho == 0) ? dy : ((rho == 1) ? dz : dx);
        const float dR2 = (rho == 0) ? dz : ((rho == 1) ? dx : dy);
        float* fpb = out_fp + (size_t)ray * (NS * 3);
        const float2* c2 = (const float2*)(colors + (size_t)ray * (NS * 3));

        #pragma unroll
        for (int i = 0; i < 9; i++) {
            const float2 cvi = __ldg(&c2[32 * i + L]);
            const int e0  = 64 * i + 2 * L;
            const int s0  = e0 / 3;
            const int c0r = e0 - 3 * s0;
            const int s1  = s0 + (c0r == 2 ? 1 : 0);
            const float t0 = st[s0], t1 = st[s1];
            const float w0 = sw[s0], w1 = sw[s1];
            const int q0 = i % 3, q1 = (i + 1) % 3;   // compile-time slots
            const float o0 = (q0 == 0) ? oR0 : ((q0 == 1) ? oR1 : oR2);
            const float d0 = (q0 == 0) ? dR0 : ((q0 == 1) ? dR1 : dR2);
            const float o1 = (q1 == 0) ? oR0 : ((q1 == 1) ? oR1 : oR2);
            const float d1 = (q1 == 0) ? dR0 : ((q1 == 1) ? dR1 : dR2);
            *(float2*)(fpb + e0) = make_float2(o0 + d0 * t0, o1 + d1 * t1);
            const float g0 = w0 * cvi.x;
            const float g1 = w1 * cvi.y;
            if (q0 == 0) A0 += g0; else if (q0 == 1) A1 += g0; else A2 += g0;
            if (q1 == 0) A0 += g1; else if (q1 == 1) A1 += g1; else A2 += g1;
        }
    }

    // ---- H: final reductions (single warp, no shared) ----
    {
        const int i0 = (0 + L) % 3, i1 = (1 + L) % 3, i2 = (2 + L) % 3;
        float rC = (i0 == 0) ? A0 : ((i0 == 1) ? A1 : A2);
        float gC = (i1 == 0) ? A0 : ((i1 == 1) ? A1 : A2);
        float bC = (i2 == 0) ? A0 : ((i2 == 1) ? A1 : A2);
        #pragma unroll
        for (int off = 16; off; off >>= 1) {
            rC  += __shfl_xor_sync(0xffffffffu, rC,  off);
            gC  += __shfl_xor_sync(0xffffffffu, gC,  off);
            bC  += __shfl_xor_sync(0xffffffffu, bC,  off);
            dep += __shfl_xor_sync(0xffffffffu, dep, off);
            op  += __shfl_xor_sync(0xffffffffu, op,  off);
        }
        if (L == 0) {
            out_rgb[3 * ray + 0] = rC;
            out_rgb[3 * ray + 1] = gC;
            out_rgb[3 * ray + 2] = bC;
            out_depth[ray] = dep;
            out_op[ray]    = op;
        }
    }
}

extern "C" void kernel_launch(void* const* d_in, const int* in_sizes, int n_in,
                              void* d_out, int out_size)
{
    const float* ro     = (const float*)d_in[0];
    const float* rd     = (const float*)d_in[1];
    const float* cw     = (const float*)d_in[2];
    const float* ct     = (const float*)d_in[3];
    const float* u      = (const float*)d_in[4];
    const float* colors = (const float*)d_in[5];
    const float* dens   = (const float*)d_in[6];

    const int N = in_sizes[0] / 3;

    float* out       = (float*)d_out;
    float* out_rgb   = out;                 // [N,3]
    float* out_depth = out + (size_t)N * 3; // [N]
    float* out_op    = out_depth + N;       // [N]
    float* out_fp    = out_op + N;          // [N,NS,3]

    const int blocks = (N + RPB - 1) / RPB;
    gridnerf_kernel<<<blocks, 32 * RPB>>>(ro, rd, cw, ct, u, colors, dens,
                                          out_rgb, out_depth, out_op, out_fp, N);
}

// round 10
// speedup vs baseline: 1.0585x; 1.0585x over previous
#include <cuda_runtime.h>
#include <math.h>

#define NC 64
#define NF 128
#define NS 192
#define RPB 8        // rays per block, 1 warp each

// compare-exchange a pair of registers; 'up' => a gets min
#define CEPAIR(a, b, up) { float _mn = fminf(a, b), _mx = fmaxf(a, b); \
                           a = (up) ? _mn : _mx; b = (up) ? _mx : _mn; }

// rank of c in sorted su[0..127] (strict <, pads [128..191] = +inf)
#define RANK128(res, su, c) {                       \
    int _r = 0;                                     \
    if ((su)[127]      < (c)) _r = 128;             \
    if ((su)[_r + 63]  < (c)) _r += 64;             \
    if ((su)[_r + 31]  < (c)) _r += 32;             \
    if ((su)[_r + 15]  < (c)) _r += 16;             \
    if ((su)[_r + 7]   < (c)) _r += 8;              \
    if ((su)[_r + 3]   < (c)) _r += 4;              \
    if ((su)[_r + 1]   < (c)) _r += 2;              \
    if ((su)[_r]       < (c)) _r += 1;              \
    (res) = _r; }

__global__ __launch_bounds__(256, 5) void gridnerf_kernel(
    const float* __restrict__ ro,      // [N,3]
    const float* __restrict__ rd,      // [N,3]
    const float* __restrict__ cw,      // [N,NC]
    const float* __restrict__ ct,      // [N,NC]
    const float* __restrict__ uu_in,   // [N,NF]
    const float* __restrict__ colors,  // [N,NS,3]
    const float* __restrict__ dens,    // [N,NS]
    float* __restrict__ out_rgb,       // [N,3]
    float* __restrict__ out_depth,     // [N]
    float* __restrict__ out_op,        // [N]
    float* __restrict__ out_fp,        // [N,NS,3]
    int nrays)
{
    const int L   = threadIdx.x & 31;
    const int w   = threadIdx.x >> 5;
    const int ray = blockIdx.x * RPB + w;
    if (ray >= nrays) return;          // warp-uniform exit; no block barriers used

    __shared__ float2 sh_cc[RPB][64];   // (cdf[i], ct[i])
    __shared__ float  sh_u [RPB][192];  // sorted u, pads +inf
    __shared__ int    sh_mk[RPB][160];  // boundary-rank histogram
    __shared__ float  sh_t [RPB][192];  // merged sorted t
    __shared__ float2 sh_tw[RPB][192];  // (t, weight)

    float2* cc  = sh_cc[w];
    float*  su  = sh_u[w];
    int*    mk  = sh_mk[w];
    float*  st  = sh_t[w];
    float2* stw = sh_tw[w];

    // ---- A: global loads (coalesced / vectorized) ----
    const float4 u4 = ((const float4*)(uu_in + (size_t)ray * NF))[L];
    float v0 = u4.x, v1 = u4.y, v2 = u4.z, v3 = u4.w;   // elements 4L..4L+3

    const float2 cw2 = ((const float2*)(cw + (size_t)ray * NC))[L];
    const float2 ct2 = ((const float2*)(ct + (size_t)ray * NC))[L];

    const float ox = ro[3 * ray + 0], oy = ro[3 * ray + 1], oz = ro[3 * ray + 2];
    const float dx = rd[3 * ray + 0], dy = rd[3 * ray + 1], dz = rd[3 * ray + 2];
    const float dnorm = sqrtf(dx * dx + dy * dy + dz * dz);

    // ---- B: cdf build (pair-per-lane warp scan); boundaries stay in regs ----
    float cdf_b1, cdf_b2;               // cdf[2L+1], cdf[2L+2]
    {
        const float a  = cw2.x + 1e-5f;
        const float b  = cw2.y + 1e-5f;
        const float ps = a + b;
        float inc = ps;
        #pragma unroll
        for (int off = 1; off < 32; off <<= 1) {
            float n = __shfl_up_sync(0xffffffffu, inc, off);
            if (L >= off) inc += n;
        }
        const float total = __shfl_sync(0xffffffffu, inc, 31);
        const float invt  = 1.f / total;
        const float excl  = inc - ps;
        const float cdf_e = excl * invt;          // cdf[2L]
        cdf_b1 = (excl + a)  * invt;              // cdf[2L+1]
        cdf_b2 = (excl + ps) * invt;              // cdf[2L+2]
        // cc[2L] = (cdf[2L], ct[2L]); cc[2L+1] = (cdf[2L+1], ct[2L+1])
        *(float4*)(cc + 2 * L) = make_float4(cdf_e, ct2.x, cdf_b1, ct2.y);
        su[128 + L] = 3.4e38f;
        su[160 + L] = 3.4e38f;
        mk[L]       = 0;
        mk[32 + L]  = 0;
        mk[64 + L]  = 0;
        mk[96 + L]  = 0;
        mk[128 + L] = 0;
    }

    // ---- C: bitonic sort of 128 u, 4 elements/thread (e = 4L+i) ----
    #pragma unroll
    for (int k = 2; k <= 128; k <<= 1) {
        #pragma unroll
        for (int j = k >> 1; j >= 4; j >>= 1) {
            const bool up = ((L & (k >> 2)) == 0);   // k>=8 here
            const bool lw = ((L & (j >> 2)) == 0);
            const bool km = (up == lw);
            float w0 = __shfl_xor_sync(0xffffffffu, v0, j >> 2);
            float w1 = __shfl_xor_sync(0xffffffffu, v1, j >> 2);
            float w2 = __shfl_xor_sync(0xffffffffu, v2, j >> 2);
            float w3 = __shfl_xor_sync(0xffffffffu, v3, j >> 2);
            v0 = km ? fminf(v0, w0) : fmaxf(v0, w0);
            v1 = km ? fminf(v1, w1) : fmaxf(v1, w1);
            v2 = km ? fminf(v2, w2) : fmaxf(v2, w2);
            v3 = km ? fminf(v3, w3) : fmaxf(v3, w3);
        }
        if (k >= 4) {  // j = 2 : pairs (v0,v2), (v1,v3)
            const bool up = (k == 4) ? ((L & 1) == 0) : ((L & (k >> 2)) == 0);
            CEPAIR(v0, v2, up); CEPAIR(v1, v3, up);
        }
        // j = 1 : pairs (v0,v1), (v2,v3)
        if (k == 2) {
            CEPAIR(v0, v1, true);  CEPAIR(v2, v3, false);
        } else {
            const bool up = (k == 4) ? ((L & 1) == 0) : ((L & (k >> 2)) == 0);
            CEPAIR(v0, v1, up);    CEPAIR(v2, v3, up);
        }
    }
    *(float4*)(su + 4 * L) = make_float4(v0, v1, v2, v3);
    __syncwarp();

    // ---- D1: boundary ranks in sorted u; histogram + coarse scatter ----
    {
        int s1, s2;
        RANK128(s1, su, cdf_b1);   // rank of cdf[2L+1]
        RANK128(s2, su, cdf_b2);   // rank of cdf[2L+2]
        atomicAdd(&mk[s1], 1);
        atomicAdd(&mk[s2], 1);
        // coarse merge ranks: r(i=2L) comes from lane L-1's s2; r(0)=0
        int r0 = __shfl_up_sync(0xffffffffu, s2, 1);
        if (L == 0) r0 = 0;
        st[2 * L + r0]     = ct2.x;
        st[2 * L + 1 + s1] = ct2.y;
    }
    __syncwarp();

    // ---- D2: lo via prefix of histogram; interpolate + scatter fine ----
    {
        const int4 m4 = *(const int4*)(mk + 4 * L);
        const int c0 = m4.x;
        const int c1 = c0 + m4.y;
        const int c2 = c1 + m4.z;
        const int c3 = c2 + m4.w;
        int inc = c3;
        #pragma unroll
        for (int off = 1; off < 32; off <<= 1) {
            int n = __shfl_up_sync(0xffffffffu, inc, off);
            if (L >= off) inc += n;
        }
        const int exc = inc - c3;
        const int lov[4] = {1 + exc + c0, 1 + exc + c1, 1 + exc + c2, 1 + exc + c3};
        const float va[4] = {v0, v1, v2, v3};
        #pragma unroll
        for (int i = 0; i < 4; i++) {
            const int   lo = lov[i];
            const float uu = va[i];
            const int below = min(lo - 1, NC - 1);
            const int above = min(lo,     NC - 1);
            const float2 ccb = cc[below];
            const float2 cca = cc[above];
            float denom = cca.x - ccb.x;
            if (denom < 1e-5f) denom = 1.f;
            const float tt = (uu - ccb.x) / denom;
            const float fv = ccb.y + tt * (cca.y - ccb.y);
            st[4 * L + i + min(lo, NC)] = fv;
        }
    }
    __syncwarp();

    // ---- F: alpha + transmittance (thread owns samples 6L..6L+5) ----
    float dep = 0.f, op = 0.f;
    {
        const float2 tA = *(const float2*)(st + 6 * L);
        const float2 tB = *(const float2*)(st + 6 * L + 2);
        const float2 tC = *(const float2*)(st + 6 * L + 4);
        const float tb[6] = {tA.x, tA.y, tB.x, tB.y, tC.x, tC.y};
        const float t6 = (L < 31) ? st[6 * L + 6] : 0.f;

        const float* dvp = dens + (size_t)ray * NS + 6 * L;
        const float2 dva = *(const float2*)(dvp + 0);
        const float2 dvb = *(const float2*)(dvp + 2);
        const float2 dvc = *(const float2*)(dvp + 4);
        const float dvv[6] = {dva.x, dva.y, dvb.x, dvb.y, dvc.x, dvc.y};

        float alpha[6];
        float run = 1.f;
        #pragma unroll
        for (int i = 0; i < 6; i++) {
            float dist;
            if (i < 5)          dist = tb[i + 1] - tb[i];
            else if (L == 31)   dist = 1e10f;
            else                dist = t6 - tb[5];
            dist *= dnorm;
            alpha[i] = 1.f - __expf(-dvv[i] * dist);
            run *= (1.f - alpha[i] + 1e-10f);
        }
        float inc = run;
        #pragma unroll
        for (int off = 1; off < 32; off <<= 1) {
            float n = __shfl_up_sync(0xffffffffu, inc, off);
            if (L >= off) inc *= n;
        }
        float wex = __shfl_up_sync(0xffffffffu, inc, 1);
        if (L == 0) wex = 1.f;

        float run2 = wex;                 // running transmittance
        #pragma unroll
        for (int i = 0; i < 6; i++) {
            const float wt = alpha[i] * run2;
            stw[6 * L + i] = make_float2(tb[i], wt);
            dep += wt * tb[i];
            op  += wt;
            run2 *= (1.f - alpha[i] + 1e-10f);
        }
    }
    __syncwarp();

    // ---- G: fused coalesced fp stores + rgb accumulation ----
    float A0 = 0.f, A1 = 0.f, A2 = 0.f;
    {
        const int rho = (2 * L) % 3;
        const float oR0 = (rho == 0) ? ox : ((rho == 1) ? oy : oz);
        const float oR1 = (rho == 0) ? oy : ((rho == 1) ? oz : ox);
        const float oR2 = (rho == 0) ? oz : ((rho == 1) ? ox : oy);
        const float dR0 = (rho == 0) ? dx : ((rho == 1) ? dy : dz);
        const float dR1 = (rho == 0) ? dy : ((rho == 1) ? dz : dx);
        const float dR2 = (rho == 0) ? dz : ((rho == 1) ? dx : dy);
        float* fpb = out_fp + (size_t)ray * (NS * 3);
        const float2* c2 = (const float2*)(colors + (size_t)ray * (NS * 3));

        #pragma unroll
        for (int i = 0; i < 9; i++) {
            const float2 cvi = __ldg(&c2[32 * i + L]);
            const int e0  = 64 * i + 2 * L;
            const int s0  = e0 / 3;
            const int c0r = e0 - 3 * s0;
            const int s1  = s0 + (c0r == 2 ? 1 : 0);
            const float2 tw0 = stw[s0];
            const float2 tw1 = stw[s1];
            const int q0 = i % 3, q1 = (i + 1) % 3;   // compile-time slots
            const float o0 = (q0 == 0) ? oR0 : ((q0 == 1) ? oR1 : oR2);
            const float d0 = (q0 == 0) ? dR0 : ((q0 == 1) ? dR1 : dR2);
            const float o1 = (q1 == 0) ? oR0 : ((q1 == 1) ? oR1 : oR2);
            const float d1 = (q1 == 0) ? dR0 : ((q1 == 1) ? dR1 : dR2);
            *(float2*)(fpb + e0) = make_float2(o0 + d0 * tw0.x, o1 + d1 * tw1.x);
            const float g0 = tw0.y * cvi.x;
            const float g1 = tw1.y * cvi.y;
            if (q0 == 0) A0 += g0; else if (q0 == 1) A1 += g0; else A2 += g0;
            if (q1 == 0) A0 += g1; else if (q1 == 1) A1 += g1; else A2 += g1;
        }
    }

    // ---- H: final reductions (single warp, no shared) ----
    {
        const int i0 = (0 + L) % 3, i1 = (1 + L) % 3, i2 = (2 + L) % 3;
        float rC = (i0 == 0) ? A0 : ((i0 == 1) ? A1 : A2);
        float gC = (i1 == 0) ? A0 : ((i1 == 1) ? A1 : A2);
        float bC = (i2 == 0) ? A0 : ((i2 == 1) ? A1 : A2);
        #pragma unroll
        for (int off = 16; off; off >>= 1) {
            rC  += __shfl_xor_sync(0xffffffffu, rC,  off);
            gC  += __shfl_xor_sync(0xffffffffu, gC,  off);
            bC  += __shfl_xor_sync(0xffffffffu, bC,  off);
            dep += __shfl_xor_sync(0xffffffffu, dep, off);
            op  += __shfl_xor_sync(0xffffffffu, op,  off);
        }
        if (L == 0) {
            out_rgb[3 * ray + 0] = rC;
            out_rgb[3 * ray + 1] = gC;
            out_rgb[3 * ray + 2] = bC;
            out_depth[ray] = dep;
            out_op[ray]    = op;
        }
    }
}

extern "C" void kernel_launch(void* const* d_in, const int* in_sizes, int n_in,
                              void* d_out, int out_size)
{
    const float* ro     = (const float*)d_in[0];
    const float* rd     = (const float*)d_in[1];
    const float* cw     = (const float*)d_in[2];
    const float* ct     = (const float*)d_in[3];
    const float* u      = (const float*)d_in[4];
    const float* colors = (const float*)d_in[5];
    const float* dens   = (const float*)d_in[6];

    const int N = in_sizes[0] / 3;

    float* out       = (float*)d_out;
    float* out_rgb   = out;                 // [N,3]
    float* out_depth = out + (size_t)N * 3; // [N]
    float* out_op    = out_depth + N;       // [N]
    float* out_fp    = out_op + N;          // [N,NS,3]

    const int blocks = (N + RPB - 1) / RPB;
    gridnerf_kernel<<<blocks, 32 * RPB>>>(ro, rd, cw, ct, u, colors, dens,
                                          out_rgb, out_depth, out_op, out_fp, N);
}